// round 16
// baseline (speedup 1.0000x reference)
#include <cuda_runtime.h>
#include <cuda_fp16.h>
#include <math.h>
#include <stdint.h>

#define N_TOK 2304
#define CC    256
#define HEADS 8
#define DH    64
#define INNER 512
#define BATCH 4

#define QSCALE 14.4269504088896341f   // 10 * log2(e)

// Scratch (device globals; no runtime allocation allowed)
__device__ __half g_xh[(size_t)BATCH*N_TOK*CC];       // xT hi  [b][n][c]
__device__ __half g_xl[(size_t)BATCH*N_TOK*CC];       // xT lo
__device__ __half g_wh[(size_t)3*INNER*CC];           // wqkv hi [o][c]
__device__ __half g_wl[(size_t)3*INNER*CC];           // wqkv lo
__device__ __half g_woh[(size_t)CC*INNER];            // wout hi [o][ci]
__device__ __half g_wol[(size_t)CC*INNER];            // wout lo
__device__ __half g_qh[(size_t)BATCH*HEADS*N_TOK*DH]; // [b][h][n][d]  l2norm'd * 10*log2e
__device__ __half g_kh[(size_t)BATCH*HEADS*N_TOK*DH]; // [b][h][n][d]  l2norm'd
__device__ __half g_vT[(size_t)BATCH*HEADS*DH*N_TOK]; // [b][h][d][n]  (V transposed)
__device__ __half g_ah[(size_t)BATCH*N_TOK*INNER];    // attention out hi [b][n][ci]
__device__ __half g_al[(size_t)BATCH*N_TOK*INNER];    // attention out lo

__device__ __forceinline__ uint32_t smem_u32(const void* p) {
    uint32_t a;
    asm("{ .reg .u64 t; cvta.to.shared.u64 t, %1; cvt.u32.u64 %0, t; }" : "=r"(a) : "l"(p));
    return a;
}
__device__ __forceinline__ void cp16(uint32_t dst, const void* src) {
    asm volatile("cp.async.cg.shared.global [%0], [%1], 16;" :: "r"(dst), "l"(src) : "memory");
}
#define CP_COMMIT() asm volatile("cp.async.commit_group;" ::: "memory")
#define CP_WAIT0()  asm volatile("cp.async.wait_group 0;" ::: "memory")

__device__ __forceinline__ uint32_t pack_h2(float a, float b) {
    __half2 h = __floats2half2_rn(a, b);
    return *(uint32_t*)&h;
}
__device__ __forceinline__ uint32_t pack2h(__half a, __half b) {
    __half2 h = __halves2half2(a, b);
    return *(uint32_t*)&h;
}

// Warp-level fp16 MMA: D(16x8,f32) += A(16x16,f16) * B(16x8,f16), row.col
__device__ __forceinline__ void mma_f16(float c[4],
                                        uint32_t a0, uint32_t a1, uint32_t a2, uint32_t a3,
                                        uint32_t b0, uint32_t b1) {
    asm volatile(
        "mma.sync.aligned.m16n8k16.row.col.f32.f16.f16.f32 "
        "{%0,%1,%2,%3}, {%4,%5,%6,%7}, {%8,%9}, {%0,%1,%2,%3};"
        : "+f"(c[0]), "+f"(c[1]), "+f"(c[2]), "+f"(c[3])
        : "r"(a0), "r"(a1), "r"(a2), "r"(a3), "r"(b0), "r"(b1));
}

// ---------------------------------------------------------------------------
// Kernel 0a: split weights to hi/lo fp16
// ---------------------------------------------------------------------------
__global__ __launch_bounds__(256) void convert_w_kernel(const float* __restrict__ wqkv,
                                                        const float* __restrict__ wout) {
    int i = blockIdx.x * 256 + threadIdx.x;
    const int NW = 3 * INNER * CC;
    if (i < NW) {
        float v = wqkv[i];
        __half h = __float2half_rn(v);
        g_wh[i] = h;
        g_wl[i] = __float2half_rn(v - __half2float(h));
    } else {
        int j = i - NW;
        if (j < CC * INNER) {
            float v = wout[j];
            __half h = __float2half_rn(v);
            g_woh[j] = h;
            g_wol[j] = __float2half_rn(v - __half2float(h));
        }
    }
}

// ---------------------------------------------------------------------------
// Kernel 0b: transpose + split x: [b][c][n] fp32 -> [b][n][c] hi/lo fp16
// ---------------------------------------------------------------------------
__global__ __launch_bounds__(256) void convert_x_kernel(const float* __restrict__ x) {
    __shared__ float sm[32][33];
    const int nt = blockIdx.x, ct = blockIdx.y, b = blockIdx.z;
    const int tx = threadIdx.x & 31, ty = threadIdx.x >> 5;

    const float* xb = x + ((size_t)b * CC + ct * 32) * N_TOK + nt * 32;
#pragma unroll
    for (int k = 0; k < 4; k++)
        sm[ty + k * 8][tx] = xb[(size_t)(ty + k * 8) * N_TOK + tx];
    __syncthreads();

#pragma unroll
    for (int k = 0; k < 4; k++) {
        int nl = ty + k * 8;
        float v = sm[tx][nl];
        __half h = __float2half_rn(v);
        size_t idx = ((size_t)b * N_TOK + nt * 32 + nl) * CC + ct * 32 + tx;
        g_xh[idx] = h;
        g_xl[idx] = __float2half_rn(v - __half2float(h));
    }
}

// ---------------------------------------------------------------------------
// Kernel A: QKV projection via split-fp16 mma (3-term), double-buffered.
// 128 threads, 4 warps, warp tile 32 tokens x 64 o (crossbar-traffic halved).
// ---------------------------------------------------------------------------
#define QPADC 72
#define QXH_OFF 0
#define QXL_OFF (128 * QPADC)
#define QWH_OFF (2 * 128 * QPADC)
#define QWL_OFF (2 * 128 * QPADC + 64 * QPADC)
#define QSTAGE_H (2 * 128 * QPADC + 2 * 64 * QPADC)   // 27648 halfs
#define QSMEM_BYTES (2 * QSTAGE_H * 2)                // 110592 B
#define PADT 136

extern __shared__ char qkv_smem[];
__global__ __launch_bounds__(128, 2) void qkv_mma_kernel() {
    const int nt = blockIdx.x;      // 0..17
    const int oy = blockIdx.y;      // 0..23
    const int b  = blockIdx.z;
    const int n0 = nt * 128;
    const int o0 = oy * 64;
    const int p  = oy >> 3;
    const int h  = oy & 7;

    const int t    = threadIdx.x;
    const int lane = t & 31;
    const int wid  = t >> 5;        // 0..3
    const int r    = lane >> 2;
    const int cl   = lane & 3;
    const int wt   = wid * 32;      // warp token base

    // loaders: X row per thread; W half-row per thread
    const __half* Xh = g_xh + ((size_t)b * N_TOK + n0 + t) * CC;
    const __half* Xl = g_xl + ((size_t)b * N_TOK + n0 + t) * CC;
    const int wr = t >> 1, wseg = (t & 1) * 32;
    const __half* Wh = g_wh + (size_t)(o0 + wr) * CC + wseg;
    const __half* Wl = g_wl + (size_t)(o0 + wr) * CC + wseg;

    const uint32_t sbase = smem_u32(qkv_smem);
    const uint32_t xdh = sbase + (QXH_OFF + t * QPADC) * 2;
    const uint32_t xdl = sbase + (QXL_OFF + t * QPADC) * 2;
    const uint32_t wdh = sbase + (QWH_OFF + wr * QPADC + wseg) * 2;
    const uint32_t wdl = sbase + (QWL_OFF + wr * QPADC + wseg) * 2;

    float acc[16][4] = {};   // [mi*8+nb][4]

    // prologue: stage 0
    {
#pragma unroll
        for (int k = 0; k < 8; k++) {
            cp16(xdh + k * 16, Xh + k * 8);
            cp16(xdl + k * 16, Xl + k * 8);
        }
#pragma unroll
        for (int k = 0; k < 4; k++) {
            cp16(wdh + k * 16, Wh + k * 8);
            cp16(wdl + k * 16, Wl + k * 8);
        }
        CP_COMMIT();
    }

    for (int it = 0; it < 4; it++) {
        const uint32_t stB = (uint32_t)(it & 1) * (QSTAGE_H * 2);
        CP_WAIT0();
        __syncthreads();

        if (it < 3) {
            const int c1 = (it + 1) * 64;
            const uint32_t nsB = (uint32_t)((it + 1) & 1) * (QSTAGE_H * 2);
#pragma unroll
            for (int k = 0; k < 8; k++) {
                cp16(xdh + nsB + k * 16, Xh + c1 + k * 8);
                cp16(xdl + nsB + k * 16, Xl + c1 + k * 8);
            }
#pragma unroll
            for (int k = 0; k < 4; k++) {
                cp16(wdh + nsB + k * 16, Wh + c1 + k * 8);
                cp16(wdl + nsB + k * 16, Wl + c1 + k * 8);
            }
            CP_COMMIT();
        }

        const __half* sXh = (const __half*)(qkv_smem + stB) + QXH_OFF;
        const __half* sXl = (const __half*)(qkv_smem + stB) + QXL_OFF;
        const __half* sWh = (const __half*)(qkv_smem + stB) + QWH_OFF;
        const __half* sWl = (const __half*)(qkv_smem + stB) + QWL_OFF;

#pragma unroll
        for (int kc = 0; kc < 4; kc++) {
            uint32_t ah[2][4], al[2][4];
#pragma unroll
            for (int mi = 0; mi < 2; mi++) {
                const int rw = wt + mi * 16 + r;
                ah[mi][0] = *(uint32_t*)&sXh[rw * QPADC + kc * 16 + 2 * cl];
                ah[mi][1] = *(uint32_t*)&sXh[(rw + 8) * QPADC + kc * 16 + 2 * cl];
                ah[mi][2] = *(uint32_t*)&sXh[rw * QPADC + kc * 16 + 2 * cl + 8];
                ah[mi][3] = *(uint32_t*)&sXh[(rw + 8) * QPADC + kc * 16 + 2 * cl + 8];
                al[mi][0] = *(uint32_t*)&sXl[rw * QPADC + kc * 16 + 2 * cl];
                al[mi][1] = *(uint32_t*)&sXl[(rw + 8) * QPADC + kc * 16 + 2 * cl];
                al[mi][2] = *(uint32_t*)&sXl[rw * QPADC + kc * 16 + 2 * cl + 8];
                al[mi][3] = *(uint32_t*)&sXl[(rw + 8) * QPADC + kc * 16 + 2 * cl + 8];
            }
#pragma unroll
            for (int nb = 0; nb < 8; nb++) {
                uint32_t bh0 = *(uint32_t*)&sWh[(nb * 8 + r) * QPADC + kc * 16 + 2 * cl];
                uint32_t bh1 = *(uint32_t*)&sWh[(nb * 8 + r) * QPADC + kc * 16 + 2 * cl + 8];
                uint32_t bl0 = *(uint32_t*)&sWl[(nb * 8 + r) * QPADC + kc * 16 + 2 * cl];
                uint32_t bl1 = *(uint32_t*)&sWl[(nb * 8 + r) * QPADC + kc * 16 + 2 * cl + 8];
#pragma unroll
                for (int mi = 0; mi < 2; mi++) {
                    mma_f16(acc[mi * 8 + nb], ah[mi][0], ah[mi][1], ah[mi][2], ah[mi][3], bh0, bh1);
                    mma_f16(acc[mi * 8 + nb], ah[mi][0], ah[mi][1], ah[mi][2], ah[mi][3], bl0, bl1);
                    mma_f16(acc[mi * 8 + nb], al[mi][0], al[mi][1], al[mi][2], al[mi][3], bh0, bh1);
                }
            }
        }
    }

    const int bh = b * HEADS + h;

    if (p == 2) {
        // V: transpose via smem (half) then coalesced writes to g_vT [d][n]
        __half* sVt = (__half*)qkv_smem;   // [64][PADT]
        __syncthreads();
#pragma unroll
        for (int mi = 0; mi < 2; mi++) {
            const int tr0 = wt + mi * 16 + r;
            const int tr1 = tr0 + 8;
#pragma unroll
            for (int nb = 0; nb < 8; nb++) {
                const int dc = nb * 8 + 2 * cl;
                sVt[dc * PADT + tr0]       = __float2half_rn(acc[mi * 8 + nb][0]);
                sVt[(dc + 1) * PADT + tr0] = __float2half_rn(acc[mi * 8 + nb][1]);
                sVt[dc * PADT + tr1]       = __float2half_rn(acc[mi * 8 + nb][2]);
                sVt[(dc + 1) * PADT + tr1] = __float2half_rn(acc[mi * 8 + nb][3]);
            }
        }
        __syncthreads();
        const int d = t >> 1, seg = (t & 1) * 64;
        __half* dst = g_vT + ((size_t)bh * DH + d) * N_TOK + n0 + seg;
#pragma unroll
        for (int k = 0; k < 8; k++)
            *(uint4*)&dst[k * 8] = *(uint4*)&sVt[d * PADT + seg + k * 8];
    } else {
        const float sf = (p == 0) ? QSCALE : 1.0f;   // fold SCALE*log2e into Q
        __half* dstb = (p == 0 ? g_qh : g_kh) + ((size_t)bh * N_TOK + n0) * DH;
#pragma unroll
        for (int mi = 0; mi < 2; mi++) {
            float l0 = 0.0f, l1 = 0.0f;
#pragma unroll
            for (int nb = 0; nb < 8; nb++) {
                l0 += acc[mi * 8 + nb][0] * acc[mi * 8 + nb][0] +
                      acc[mi * 8 + nb][1] * acc[mi * 8 + nb][1];
                l1 += acc[mi * 8 + nb][2] * acc[mi * 8 + nb][2] +
                      acc[mi * 8 + nb][3] * acc[mi * 8 + nb][3];
            }
            l0 += __shfl_xor_sync(0xffffffffu, l0, 1);
            l0 += __shfl_xor_sync(0xffffffffu, l0, 2);
            l1 += __shfl_xor_sync(0xffffffffu, l1, 1);
            l1 += __shfl_xor_sync(0xffffffffu, l1, 2);
            const float inv0 = sf / fmaxf(sqrtf(l0), 1e-12f);
            const float inv1 = sf / fmaxf(sqrtf(l1), 1e-12f);
            const int tr0 = wt + mi * 16 + r;
#pragma unroll
            for (int nb = 0; nb < 8; nb++) {
                *(uint32_t*)&dstb[(size_t)tr0 * DH + nb * 8 + 2 * cl] =
                    pack_h2(acc[mi * 8 + nb][0] * inv0, acc[mi * 8 + nb][1] * inv0);
                *(uint32_t*)&dstb[(size_t)(tr0 + 8) * DH + nb * 8 + 2 * cl] =
                    pack_h2(acc[mi * 8 + nb][2] * inv1, acc[mi * 8 + nb][3] * inv1);
            }
        }
    }
}

// ---------------------------------------------------------------------------
// Kernel B: fp16 m16n8k16 mma flash attention, cp.async double-buffered K/V.
// p = exp2(s) (constant exp2(-QSCALE) cancels against l in normalization).
// ---------------------------------------------------------------------------
#define PADH 72
#define KBUFB (64 * PADH * 2)
#define SK0B  0
#define SK1B  (KBUFB)
#define SVT0B (2 * KBUFB)
#define SVT1B (3 * KBUFB)
#define SQB   (4 * KBUFB)
#define ATT_SMEM_BYTES (4 * KBUFB + 128 * PADH * 2)
#define PADP 68
#define NKT (N_TOK / 64)

extern __shared__ char att_smem[];
__global__ __launch_bounds__(256, 2) void attn_mma_kernel() {
    __half* sQ = (__half*)(att_smem + SQB);
    float*  sO = (float*)att_smem;            // overlays K/VT buffers (post-loop)

    const int t    = threadIdx.x;
    const int lane = t & 31;
    const int wid  = t >> 5;
    const int qt   = blockIdx.x;
    const int h    = blockIdx.y;
    const int b    = blockIdx.z;
    const int bh   = b * HEADS + h;
    const int n0   = qt * 128;

    const int r  = lane >> 2;
    const int cl = lane & 3;
    const int qrow = wid * 16 + r;

    const int kvr = t >> 2;
    const int cw  = t & 3;
    const __half* Kgb = g_kh + ((size_t)bh * N_TOK + kvr) * DH + cw * 16;
    const __half* Vgb = g_vT + ((size_t)bh * DH + kvr) * N_TOK + cw * 16;

    const uint32_t sbase = smem_u32(att_smem);
    const uint32_t kdst[2] = { sbase + SK0B  + (kvr * PADH + cw * 16) * 2u,
                               sbase + SK1B  + (kvr * PADH + cw * 16) * 2u };
    const uint32_t vdst[2] = { sbase + SVT0B + (kvr * PADH + cw * 16) * 2u,
                               sbase + SVT1B + (kvr * PADH + cw * 16) * 2u };

    cp16(kdst[0], Kgb);      cp16(kdst[0] + 16, Kgb + 8);
    cp16(vdst[0], Vgb);      cp16(vdst[0] + 16, Vgb + 8);
    CP_COMMIT();
    {
        int row = t >> 1, cc = (t & 1) * 32;
        const uint4* src = (const uint4*)(g_qh + ((size_t)bh * N_TOK + n0 + row) * DH + cc);
        uint4* dst = (uint4*)(sQ + row * PADH + cc);
#pragma unroll
        for (int c = 0; c < 4; c++) dst[c] = src[c];
    }
    __syncthreads();

    uint32_t qa[4][4];
#pragma unroll
    for (int kb = 0; kb < 4; kb++) {
        qa[kb][0] = *(uint32_t*)&sQ[qrow * PADH + kb * 16 + 2 * cl];
        qa[kb][1] = *(uint32_t*)&sQ[(qrow + 8) * PADH + kb * 16 + 2 * cl];
        qa[kb][2] = *(uint32_t*)&sQ[qrow * PADH + kb * 16 + 2 * cl + 8];
        qa[kb][3] = *(uint32_t*)&sQ[(qrow + 8) * PADH + kb * 16 + 2 * cl + 8];
    }

    float o[8][4] = {};
    float l0 = 0.0f, l1 = 0.0f;

    for (int it = 0; it < NKT; it++) {
        const int buf = it & 1;
        CP_WAIT0();
        __syncthreads();

        if (it + 1 < NKT) {
            const __half* Kg = Kgb + (size_t)(it + 1) * 64 * DH;
            const __half* Vg = Vgb + (it + 1) * 64;
            const int nb2 = buf ^ 1;
            cp16(kdst[nb2], Kg);      cp16(kdst[nb2] + 16, Kg + 8);
            cp16(vdst[nb2], Vg);      cp16(vdst[nb2] + 16, Vg + 8);
            CP_COMMIT();
        }

        const __half* sK  = (const __half*)(att_smem + (buf ? SK1B : SK0B));
        const __half* sVT = (const __half*)(att_smem + (buf ? SVT1B : SVT0B));

        float s[8][4];
#pragma unroll
        for (int nb = 0; nb < 8; nb++) {
            s[nb][0] = s[nb][1] = s[nb][2] = s[nb][3] = 0.0f;
#pragma unroll
            for (int kb = 0; kb < 4; kb++) {
                uint32_t b0 = *(uint32_t*)&sK[(nb * 8 + r) * PADH + kb * 16 + 2 * cl];
                uint32_t b1 = *(uint32_t*)&sK[(nb * 8 + r) * PADH + kb * 16 + 2 * cl + 8];
                mma_f16(s[nb], qa[kb][0], qa[kb][1], qa[kb][2], qa[kb][3], b0, b1);
            }
        }

        uint32_t ph[8][2];
#pragma unroll
        for (int nb = 0; nb < 8; nb++) {
            float p0 = exp2f(s[nb][0]);
            float p1 = exp2f(s[nb][1]);
            float p2 = exp2f(s[nb][2]);
            float p3 = exp2f(s[nb][3]);
            l0 += p0 + p1;
            l1 += p2 + p3;
            ph[nb][0] = pack_h2(p0, p1);
            ph[nb][1] = pack_h2(p2, p3);
        }

#pragma unroll
        for (int kb = 0; kb < 4; kb++) {
            uint32_t a0 = ph[2 * kb][0];
            uint32_t a1 = ph[2 * kb][1];
            uint32_t a2 = ph[2 * kb + 1][0];
            uint32_t a3 = ph[2 * kb + 1][1];
#pragma unroll
            for (int nb = 0; nb < 8; nb++) {
                uint32_t b0 = *(uint32_t*)&sVT[(nb * 8 + r) * PADH + kb * 16 + 2 * cl];
                uint32_t b1 = *(uint32_t*)&sVT[(nb * 8 + r) * PADH + kb * 16 + 2 * cl + 8];
                mma_f16(o[nb], a0, a1, a2, a3, b0, b1);
            }
        }
    }

    l0 += __shfl_xor_sync(0xffffffffu, l0, 1);
    l0 += __shfl_xor_sync(0xffffffffu, l0, 2);
    l1 += __shfl_xor_sync(0xffffffffu, l1, 1);
    l1 += __shfl_xor_sync(0xffffffffu, l1, 2);
    const float inv0 = 1.0f / l0;
    const float inv1 = 1.0f / l1;

    __syncthreads();   // done reading K/VT buffers (sO overlays them)
#pragma unroll
    for (int nb = 0; nb < 8; nb++) {
        *(float2*)&sO[qrow * PADP + nb * 8 + 2 * cl] =
            make_float2(o[nb][0] * inv0, o[nb][1] * inv0);
        *(float2*)&sO[(qrow + 8) * PADP + nb * 8 + 2 * cl] =
            make_float2(o[nb][2] * inv1, o[nb][3] * inv1);
    }
    __syncthreads();

    // write O as hi/lo halves: g_ah/g_al [b][n0+row][h*64 + d]
    {
        const int row = t >> 1;
        const int seg = (t & 1) * 32;
        const float* src = sO + row * PADP + seg;
        const size_t base = ((size_t)b * N_TOK + n0 + row) * INNER + h * DH + seg;
#pragma unroll
        for (int c4 = 0; c4 < 4; c4++) {
            uint32_t uh[4], ul[4];
#pragma unroll
            for (int j = 0; j < 4; j++) {
                float v0 = src[c4 * 8 + 2 * j];
                float v1 = src[c4 * 8 + 2 * j + 1];
                __half h0 = __float2half_rn(v0);
                __half h1 = __float2half_rn(v1);
                uh[j] = pack2h(h0, h1);
                ul[j] = pack_h2(v0 - __half2float(h0), v1 - __half2float(h1));
            }
            *(uint4*)&g_ah[base + c4 * 8] = make_uint4(uh[0], uh[1], uh[2], uh[3]);
            *(uint4*)&g_al[base + c4 * 8] = make_uint4(ul[0], ul[1], ul[2], ul[3]);
        }
    }
}

// ---------------------------------------------------------------------------
// Kernel C: output projection via split-fp16 mma (3-term), double-buffered.
// 128 threads, 4 warps (2 o-tiles x 2 n-halves), warp tile 32 o x 64 n.
// ---------------------------------------------------------------------------
extern __shared__ char out_smem[];
__global__ __launch_bounds__(128, 2) void out_mma_kernel(const float* __restrict__ bias,
                                                         float* __restrict__ out) {
    const int nt = blockIdx.x;   // 0..17
    const int ot = blockIdx.y;   // 0..3
    const int b  = blockIdx.z;
    const int n0 = nt * 128;
    const int o0 = ot * 64;

    const int t    = threadIdx.x;
    const int lane = t & 31;
    const int wid  = t >> 5;     // 0..3
    const int wm   = wid & 1;    // o-tile
    const int wn   = wid >> 1;   // n-half
    const int r    = lane >> 2;
    const int cl   = lane & 3;

    // loaders: G row per thread; W half-row per thread
    const __half* Gh = g_ah + ((size_t)b * N_TOK + n0 + t) * INNER;
    const __half* Gl = g_al + ((size_t)b * N_TOK + n0 + t) * INNER;
    const int wr = t >> 1, wseg = (t & 1) * 32;
    const __half* Wh = g_woh + (size_t)(o0 + wr) * INNER + wseg;
    const __half* Wl = g_wol + (size_t)(o0 + wr) * INNER + wseg;

    const uint32_t sbase = smem_u32(out_smem);
    const uint32_t gdh = sbase + (QXH_OFF + t * QPADC) * 2;
    const uint32_t gdl = sbase + (QXL_OFF + t * QPADC) * 2;
    const uint32_t wdh = sbase + (QWH_OFF + wr * QPADC + wseg) * 2;
    const uint32_t wdl = sbase + (QWL_OFF + wr * QPADC + wseg) * 2;

    float acc[16][4] = {};   // [mi*8+nb][4]

    // prologue: stage 0
    {
#pragma unroll
        for (int k = 0; k < 8; k++) {
            cp16(gdh + k * 16, Gh + k * 8);
            cp16(gdl + k * 16, Gl + k * 8);
        }
#pragma unroll
        for (int k = 0; k < 4; k++) {
            cp16(wdh + k * 16, Wh + k * 8);
            cp16(wdl + k * 16, Wl + k * 8);
        }
        CP_COMMIT();
    }

    for (int it = 0; it < 8; it++) {
        const uint32_t stB = (uint32_t)(it & 1) * (QSTAGE_H * 2);
        CP_WAIT0();
        __syncthreads();

        if (it < 7) {
            const int c1 = (it + 1) * 64;
            const uint32_t nsB = (uint32_t)((it + 1) & 1) * (QSTAGE_H * 2);
#pragma unroll
            for (int k = 0; k < 8; k++) {
                cp16(gdh + nsB + k * 16, Gh + c1 + k * 8);
                cp16(gdl + nsB + k * 16, Gl + c1 + k * 8);
            }
#pragma unroll
            for (int k = 0; k < 4; k++) {
                cp16(wdh + nsB + k * 16, Wh + c1 + k * 8);
                cp16(wdl + nsB + k * 16, Wl + c1 + k * 8);
            }
            CP_COMMIT();
        }

        const __half* sGh = (const __half*)(out_smem + stB) + QXH_OFF;
        const __half* sGl = (const __half*)(out_smem + stB) + QXL_OFF;
        const __half* sWh = (const __half*)(out_smem + stB) + QWH_OFF;
        const __half* sWl = (const __half*)(out_smem + stB) + QWL_OFF;

#pragma unroll
        for (int kc = 0; kc < 4; kc++) {
            uint32_t ah[2][4], al[2][4];
#pragma unroll
            for (int mi = 0; mi < 2; mi++) {
                const int orow = wm * 32 + mi * 16 + r;
                ah[mi][0] = *(uint32_t*)&sWh[orow * QPADC + kc * 16 + 2 * cl];
                ah[mi][1] = *(uint32_t*)&sWh[(orow + 8) * QPADC + kc * 16 + 2 * cl];
                ah[mi][2] = *(uint32_t*)&sWh[orow * QPADC + kc * 16 + 2 * cl + 8];
                ah[mi][3] = *(uint32_t*)&sWh[(orow + 8) * QPADC + kc * 16 + 2 * cl + 8];
                al[mi][0] = *(uint32_t*)&sWl[orow * QPADC + kc * 16 + 2 * cl];
                al[mi][1] = *(uint32_t*)&sWl[(orow + 8) * QPADC + kc * 16 + 2 * cl];
                al[mi][2] = *(uint32_t*)&sWl[orow * QPADC + kc * 16 + 2 * cl + 8];
                al[mi][3] = *(uint32_t*)&sWl[(orow + 8) * QPADC + kc * 16 + 2 * cl + 8];
            }
#pragma unroll
            for (int nb = 0; nb < 8; nb++) {
                const int gn = wn * 64 + nb * 8 + r;
                uint32_t bh0 = *(uint32_t*)&sGh[gn * QPADC + kc * 16 + 2 * cl];
                uint32_t bh1 = *(uint32_t*)&sGh[gn * QPADC + kc * 16 + 2 * cl + 8];
                uint32_t bl0 = *(uint32_t*)&sGl[gn * QPADC + kc * 16 + 2 * cl];
                uint32_t bl1 = *(uint32_t*)&sGl[gn * QPADC + kc * 16 + 2 * cl + 8];
#pragma unroll
                for (int mi = 0; mi < 2; mi++) {
                    mma_f16(acc[mi * 8 + nb], ah[mi][0], ah[mi][1], ah[mi][2], ah[mi][3], bh0, bh1);
                    mma_f16(acc[mi * 8 + nb], ah[mi][0], ah[mi][1], ah[mi][2], ah[mi][3], bl0, bl1);
                    mma_f16(acc[mi * 8 + nb], al[mi][0], al[mi][1], al[mi][2], al[mi][3], bh0, bh1);
                }
            }
        }
    }

#pragma unroll
    for (int mi = 0; mi < 2; mi++) {
        const int o_g = o0 + wm * 32 + mi * 16 + r;
        const float bi0 = bias[o_g];
        const float bi1 = bias[o_g + 8];
        float* ob0 = out + ((size_t)b * CC + o_g) * N_TOK + n0 + wn * 64;
        float* ob1 = ob0 + 8 * N_TOK;
#pragma unroll
        for (int nb = 0; nb < 8; nb++) {
            *(float2*)&ob0[nb * 8 + 2 * cl] =
                make_float2(acc[mi * 8 + nb][0] + bi0, acc[mi * 8 + nb][1] + bi0);
            *(float2*)&ob1[nb * 8 + 2 * cl] =
                make_float2(acc[mi * 8 + nb][2] + bi1, acc[mi * 8 + nb][3] + bi1);
        }
    }
}

// ---------------------------------------------------------------------------
extern "C" void kernel_launch(void* const* d_in, const int* in_sizes, int n_in,
                              void* d_out, int out_size) {
    const float* x    = (const float*)d_in[0];
    const float* wqkv = (const float*)d_in[1];
    const float* wout = (const float*)d_in[2];
    const float* bout = (const float*)d_in[3];
    float* out = (float*)d_out;

    (void)in_sizes; (void)n_in; (void)out_size;

    cudaFuncSetAttribute(qkv_mma_kernel, cudaFuncAttributeMaxDynamicSharedMemorySize,
                         QSMEM_BYTES);
    cudaFuncSetAttribute(attn_mma_kernel, cudaFuncAttributeMaxDynamicSharedMemorySize,
                         ATT_SMEM_BYTES);
    cudaFuncSetAttribute(out_mma_kernel, cudaFuncAttributeMaxDynamicSharedMemorySize,
                         QSMEM_BYTES);

    convert_w_kernel<<<(3 * INNER * CC + CC * INNER) / 256, 256>>>(wqkv, wout);
    convert_x_kernel<<<dim3(N_TOK / 32, CC / 32, BATCH), 256>>>(x);
    qkv_mma_kernel<<<dim3(18, 24, 4), 128, QSMEM_BYTES>>>();
    attn_mma_kernel<<<dim3(18, 8, 4), 256, ATT_SMEM_BYTES>>>();
    out_mma_kernel<<<dim3(18, 4, 4), 128, QSMEM_BYTES>>>(bout, out);
}

// round 17
// speedup vs baseline: 1.0493x; 1.0493x over previous
#include <cuda_runtime.h>
#include <cuda_fp16.h>
#include <math.h>
#include <stdint.h>

#define N_TOK 2304
#define CC    256
#define HEADS 8
#define DH    64
#define INNER 512
#define BATCH 4

#define QSCALE 14.4269504088896341f   // 10 * log2(e)

// Scratch (device globals; no runtime allocation allowed)
__device__ __half g_xh[(size_t)BATCH*N_TOK*CC];       // xT hi  [b][n][c]
__device__ __half g_xl[(size_t)BATCH*N_TOK*CC];       // xT lo
__device__ __half g_wh[(size_t)3*INNER*CC];           // wqkv hi [o][c]
__device__ __half g_wl[(size_t)3*INNER*CC];           // wqkv lo
__device__ __half g_woh[(size_t)CC*INNER];            // wout hi [o][ci]
__device__ __half g_wol[(size_t)CC*INNER];            // wout lo
__device__ __half g_qh[(size_t)BATCH*HEADS*N_TOK*DH]; // [b][h][n][d]  l2norm'd * 10*log2e
__device__ __half g_kh[(size_t)BATCH*HEADS*N_TOK*DH]; // [b][h][n][d]  l2norm'd
__device__ __half g_vT[(size_t)BATCH*HEADS*DH*N_TOK]; // [b][h][d][n]  (V transposed)
__device__ __half g_ah[(size_t)BATCH*N_TOK*INNER];    // attention out hi [b][n][ci]
__device__ __half g_al[(size_t)BATCH*N_TOK*INNER];    // attention out lo

__device__ __forceinline__ uint32_t smem_u32(const void* p) {
    uint32_t a;
    asm("{ .reg .u64 t; cvta.to.shared.u64 t, %1; cvt.u32.u64 %0, t; }" : "=r"(a) : "l"(p));
    return a;
}
__device__ __forceinline__ void cp16(uint32_t dst, const void* src) {
    asm volatile("cp.async.cg.shared.global [%0], [%1], 16;" :: "r"(dst), "l"(src) : "memory");
}
#define CP_COMMIT() asm volatile("cp.async.commit_group;" ::: "memory")
#define CP_WAIT0()  asm volatile("cp.async.wait_group 0;" ::: "memory")

__device__ __forceinline__ uint32_t pack_h2(float a, float b) {
    __half2 h = __floats2half2_rn(a, b);
    return *(uint32_t*)&h;
}
__device__ __forceinline__ uint32_t pack2h(__half a, __half b) {
    __half2 h = __halves2half2(a, b);
    return *(uint32_t*)&h;
}

// Warp-level fp16 MMA: D(16x8,f32) += A(16x16,f16) * B(16x8,f16), row.col
__device__ __forceinline__ void mma_f16(float c[4],
                                        uint32_t a0, uint32_t a1, uint32_t a2, uint32_t a3,
                                        uint32_t b0, uint32_t b1) {
    asm volatile(
        "mma.sync.aligned.m16n8k16.row.col.f32.f16.f16.f32 "
        "{%0,%1,%2,%3}, {%4,%5,%6,%7}, {%8,%9}, {%0,%1,%2,%3};"
        : "+f"(c[0]), "+f"(c[1]), "+f"(c[2]), "+f"(c[3])
        : "r"(a0), "r"(a1), "r"(a2), "r"(a3), "r"(b0), "r"(b1));
}

// ---------------------------------------------------------------------------
// Kernel 0a: split weights to hi/lo fp16
// ---------------------------------------------------------------------------
__global__ __launch_bounds__(256) void convert_w_kernel(const float* __restrict__ wqkv,
                                                        const float* __restrict__ wout) {
    int i = blockIdx.x * 256 + threadIdx.x;
    const int NW = 3 * INNER * CC;
    if (i < NW) {
        float v = wqkv[i];
        __half h = __float2half_rn(v);
        g_wh[i] = h;
        g_wl[i] = __float2half_rn(v - __half2float(h));
    } else {
        int j = i - NW;
        if (j < CC * INNER) {
            float v = wout[j];
            __half h = __float2half_rn(v);
            g_woh[j] = h;
            g_wol[j] = __float2half_rn(v - __half2float(h));
        }
    }
}

// ---------------------------------------------------------------------------
// Kernel 0b: transpose + split x: [b][c][n] fp32 -> [b][n][c] hi/lo fp16
// ---------------------------------------------------------------------------
__global__ __launch_bounds__(256) void convert_x_kernel(const float* __restrict__ x) {
    __shared__ float sm[32][33];
    const int nt = blockIdx.x, ct = blockIdx.y, b = blockIdx.z;
    const int tx = threadIdx.x & 31, ty = threadIdx.x >> 5;

    const float* xb = x + ((size_t)b * CC + ct * 32) * N_TOK + nt * 32;
#pragma unroll
    for (int k = 0; k < 4; k++)
        sm[ty + k * 8][tx] = xb[(size_t)(ty + k * 8) * N_TOK + tx];
    __syncthreads();

#pragma unroll
    for (int k = 0; k < 4; k++) {
        int nl = ty + k * 8;
        float v = sm[tx][nl];
        __half h = __float2half_rn(v);
        size_t idx = ((size_t)b * N_TOK + nt * 32 + nl) * CC + ct * 32 + tx;
        g_xh[idx] = h;
        g_xl[idx] = __float2half_rn(v - __half2float(h));
    }
}

// ---------------------------------------------------------------------------
// Kernel A: QKV projection via split-fp16 mma (3-term), double-buffered.
// C[n][o] = xT[n][c] . W[o][c]^T. CTA: 128 tokens x 64 o. Fused l2norm.
// (R15 version: 256 threads, 8 warps x 16 token-rows.)
// ---------------------------------------------------------------------------
#define QPADC 72
#define QXH_OFF 0
#define QXL_OFF (128 * QPADC)
#define QWH_OFF (2 * 128 * QPADC)
#define QWL_OFF (2 * 128 * QPADC + 64 * QPADC)
#define QSTAGE_H (2 * 128 * QPADC + 2 * 64 * QPADC)   // 27648 halfs
#define QSMEM_BYTES (2 * QSTAGE_H * 2)                // 110592 B
#define PADT 136

extern __shared__ char qkv_smem[];
__global__ __launch_bounds__(256, 2) void qkv_mma_kernel() {
    const int nt = blockIdx.x;      // 0..17
    const int oy = blockIdx.y;      // 0..23
    const int b  = blockIdx.z;
    const int n0 = nt * 128;
    const int o0 = oy * 64;
    const int p  = oy >> 3;
    const int h  = oy & 7;

    const int t    = threadIdx.x;
    const int lane = t & 31;
    const int wid  = t >> 5;
    const int r    = lane >> 2;
    const int cl   = lane & 3;
    const int qrow = wid * 16 + r;

    // loaders
    const int xrow = t >> 1, xseg = (t & 1) * 32;
    const int wr = t >> 2, wseg = (t & 3) * 16;
    const __half* Xh = g_xh + ((size_t)b * N_TOK + n0 + xrow) * CC + xseg;
    const __half* Xl = g_xl + ((size_t)b * N_TOK + n0 + xrow) * CC + xseg;
    const __half* Wh = g_wh + (size_t)(o0 + wr) * CC + wseg;
    const __half* Wl = g_wl + (size_t)(o0 + wr) * CC + wseg;

    const uint32_t sbase = smem_u32(qkv_smem);
    const uint32_t xdh = sbase + (QXH_OFF + xrow * QPADC + xseg) * 2;
    const uint32_t xdl = sbase + (QXL_OFF + xrow * QPADC + xseg) * 2;
    const uint32_t wdh = sbase + (QWH_OFF + wr * QPADC + wseg) * 2;
    const uint32_t wdl = sbase + (QWL_OFF + wr * QPADC + wseg) * 2;

    float acc[8][4] = {};

    // prologue: stage 0
    {
#pragma unroll
        for (int k = 0; k < 4; k++) {
            cp16(xdh + k * 16, Xh + k * 8);
            cp16(xdl + k * 16, Xl + k * 8);
        }
        cp16(wdh, Wh);      cp16(wdh + 16, Wh + 8);
        cp16(wdl, Wl);      cp16(wdl + 16, Wl + 8);
        CP_COMMIT();
    }

    for (int it = 0; it < 4; it++) {
        const uint32_t stB = (uint32_t)(it & 1) * (QSTAGE_H * 2);
        CP_WAIT0();
        __syncthreads();

        if (it < 3) {
            const int c1 = (it + 1) * 64;
            const uint32_t nsB = (uint32_t)((it + 1) & 1) * (QSTAGE_H * 2);
#pragma unroll
            for (int k = 0; k < 4; k++) {
                cp16(xdh + nsB + k * 16, Xh + c1 + k * 8);
                cp16(xdl + nsB + k * 16, Xl + c1 + k * 8);
            }
            cp16(wdh + nsB, Wh + c1);      cp16(wdh + nsB + 16, Wh + c1 + 8);
            cp16(wdl + nsB, Wl + c1);      cp16(wdl + nsB + 16, Wl + c1 + 8);
            CP_COMMIT();
        }

        const __half* sXh = (const __half*)(qkv_smem + stB) + QXH_OFF;
        const __half* sXl = (const __half*)(qkv_smem + stB) + QXL_OFF;
        const __half* sWh = (const __half*)(qkv_smem + stB) + QWH_OFF;
        const __half* sWl = (const __half*)(qkv_smem + stB) + QWL_OFF;

#pragma unroll
        for (int kc = 0; kc < 4; kc++) {
            uint32_t ah[4], al[4];
            ah[0] = *(uint32_t*)&sXh[qrow * QPADC + kc * 16 + 2 * cl];
            ah[1] = *(uint32_t*)&sXh[(qrow + 8) * QPADC + kc * 16 + 2 * cl];
            ah[2] = *(uint32_t*)&sXh[qrow * QPADC + kc * 16 + 2 * cl + 8];
            ah[3] = *(uint32_t*)&sXh[(qrow + 8) * QPADC + kc * 16 + 2 * cl + 8];
            al[0] = *(uint32_t*)&sXl[qrow * QPADC + kc * 16 + 2 * cl];
            al[1] = *(uint32_t*)&sXl[(qrow + 8) * QPADC + kc * 16 + 2 * cl];
            al[2] = *(uint32_t*)&sXl[qrow * QPADC + kc * 16 + 2 * cl + 8];
            al[3] = *(uint32_t*)&sXl[(qrow + 8) * QPADC + kc * 16 + 2 * cl + 8];
#pragma unroll
            for (int ob = 0; ob < 8; ob++) {
                uint32_t bh0 = *(uint32_t*)&sWh[(ob * 8 + r) * QPADC + kc * 16 + 2 * cl];
                uint32_t bh1 = *(uint32_t*)&sWh[(ob * 8 + r) * QPADC + kc * 16 + 2 * cl + 8];
                uint32_t bl0 = *(uint32_t*)&sWl[(ob * 8 + r) * QPADC + kc * 16 + 2 * cl];
                uint32_t bl1 = *(uint32_t*)&sWl[(ob * 8 + r) * QPADC + kc * 16 + 2 * cl + 8];
                mma_f16(acc[ob], ah[0], ah[1], ah[2], ah[3], bh0, bh1);
                mma_f16(acc[ob], ah[0], ah[1], ah[2], ah[3], bl0, bl1);
                mma_f16(acc[ob], al[0], al[1], al[2], al[3], bh0, bh1);
            }
        }
    }

    const int bh = b * HEADS + h;

    if (p == 2) {
        // V: transpose via smem (half) then coalesced writes to g_vT [d][n]
        __half* sVt = (__half*)qkv_smem;   // [64][PADT]
        __syncthreads();
#pragma unroll
        for (int ob = 0; ob < 8; ob++) {
            int d = ob * 8 + 2 * cl;
            sVt[d * PADT + qrow]           = __float2half_rn(acc[ob][0]);
            sVt[(d + 1) * PADT + qrow]     = __float2half_rn(acc[ob][1]);
            sVt[d * PADT + qrow + 8]       = __float2half_rn(acc[ob][2]);
            sVt[(d + 1) * PADT + qrow + 8] = __float2half_rn(acc[ob][3]);
        }
        __syncthreads();
        const int d = t >> 2, seg = (t & 3) * 32;
        const uint4* src = (const uint4*)&sVt[d * PADT + seg];
        __half* dst = g_vT + ((size_t)bh * DH + d) * N_TOK + n0 + seg;
#pragma unroll
        for (int k = 0; k < 4; k++)
            *(uint4*)&dst[k * 8] = src[k];
    } else {
        // l2norm per token row (in-thread over 8 ob + quad shuffle)
        float l0 = 0.0f, l1 = 0.0f;
#pragma unroll
        for (int ob = 0; ob < 8; ob++) {
            l0 += acc[ob][0] * acc[ob][0] + acc[ob][1] * acc[ob][1];
            l1 += acc[ob][2] * acc[ob][2] + acc[ob][3] * acc[ob][3];
        }
        l0 += __shfl_xor_sync(0xffffffffu, l0, 1);
        l0 += __shfl_xor_sync(0xffffffffu, l0, 2);
        l1 += __shfl_xor_sync(0xffffffffu, l1, 1);
        l1 += __shfl_xor_sync(0xffffffffu, l1, 2);
        const float sf = (p == 0) ? QSCALE : 1.0f;   // fold SCALE*log2e into Q
        const float inv0 = sf / fmaxf(sqrtf(l0), 1e-12f);
        const float inv1 = sf / fmaxf(sqrtf(l1), 1e-12f);

        __half* dstb = (p == 0 ? g_qh : g_kh) + ((size_t)bh * N_TOK + n0) * DH;
#pragma unroll
        for (int ob = 0; ob < 8; ob++) {
            *(uint32_t*)&dstb[(size_t)qrow * DH + ob * 8 + 2 * cl] =
                pack_h2(acc[ob][0] * inv0, acc[ob][1] * inv0);
            *(uint32_t*)&dstb[(size_t)(qrow + 8) * DH + ob * 8 + 2 * cl] =
                pack_h2(acc[ob][2] * inv1, acc[ob][3] * inv1);
        }
    }
}

// ---------------------------------------------------------------------------
// Kernel B: fp16 m16n8k16 mma flash attention, cp.async double-buffered K/V.
// Register-lean restructure (transient s4, immediate exp2) to allow 3 CTAs/SM.
// p = exp2(s) (constant factor cancels against l).
// ---------------------------------------------------------------------------
#define PADH 72
#define KBUFB (64 * PADH * 2)
#define SK0B  0
#define SK1B  (KBUFB)
#define SVT0B (2 * KBUFB)
#define SVT1B (3 * KBUFB)
#define SQB   (4 * KBUFB)
#define ATT_SMEM_BYTES (4 * KBUFB + 128 * PADH * 2)
#define PADP 68
#define NKT (N_TOK / 64)

extern __shared__ char att_smem[];
__global__ __launch_bounds__(256, 3) void attn_mma_kernel() {
    __half* sQ = (__half*)(att_smem + SQB);
    float*  sO = (float*)att_smem;            // overlays K/VT buffers (post-loop)

    const int t    = threadIdx.x;
    const int lane = t & 31;
    const int wid  = t >> 5;
    const int qt   = blockIdx.x;
    const int h    = blockIdx.y;
    const int b    = blockIdx.z;
    const int bh   = b * HEADS + h;
    const int n0   = qt * 128;

    const int r  = lane >> 2;
    const int cl = lane & 3;
    const int qrow = wid * 16 + r;

    const int kvr = t >> 2;
    const int cw  = t & 3;
    const __half* Kgb = g_kh + ((size_t)bh * N_TOK + kvr) * DH + cw * 16;
    const __half* Vgb = g_vT + ((size_t)bh * DH + kvr) * N_TOK + cw * 16;

    const uint32_t sbase = smem_u32(att_smem);
    const uint32_t kdst[2] = { sbase + SK0B  + (kvr * PADH + cw * 16) * 2u,
                               sbase + SK1B  + (kvr * PADH + cw * 16) * 2u };
    const uint32_t vdst[2] = { sbase + SVT0B + (kvr * PADH + cw * 16) * 2u,
                               sbase + SVT1B + (kvr * PADH + cw * 16) * 2u };

    cp16(kdst[0], Kgb);      cp16(kdst[0] + 16, Kgb + 8);
    cp16(vdst[0], Vgb);      cp16(vdst[0] + 16, Vgb + 8);
    CP_COMMIT();
    {
        int row = t >> 1, cc = (t & 1) * 32;
        const uint4* src = (const uint4*)(g_qh + ((size_t)bh * N_TOK + n0 + row) * DH + cc);
        uint4* dst = (uint4*)(sQ + row * PADH + cc);
#pragma unroll
        for (int c = 0; c < 4; c++) dst[c] = src[c];
    }
    __syncthreads();

    uint32_t qa[4][4];
#pragma unroll
    for (int kb = 0; kb < 4; kb++) {
        qa[kb][0] = *(uint32_t*)&sQ[qrow * PADH + kb * 16 + 2 * cl];
        qa[kb][1] = *(uint32_t*)&sQ[(qrow + 8) * PADH + kb * 16 + 2 * cl];
        qa[kb][2] = *(uint32_t*)&sQ[qrow * PADH + kb * 16 + 2 * cl + 8];
        qa[kb][3] = *(uint32_t*)&sQ[(qrow + 8) * PADH + kb * 16 + 2 * cl + 8];
    }

    float o[8][4] = {};
    float l0 = 0.0f, l1 = 0.0f;

    for (int it = 0; it < NKT; it++) {
        const int buf = it & 1;
        CP_WAIT0();
        __syncthreads();

        if (it + 1 < NKT) {
            const __half* Kg = Kgb + (size_t)(it + 1) * 64 * DH;
            const __half* Vg = Vgb + (it + 1) * 64;
            const int nb2 = buf ^ 1;
            cp16(kdst[nb2], Kg);      cp16(kdst[nb2] + 16, Kg + 8);
            cp16(vdst[nb2], Vg);      cp16(vdst[nb2] + 16, Vg + 8);
            CP_COMMIT();
        }

        const __half* sK  = (const __half*)(att_smem + (buf ? SK1B : SK0B));
        const __half* sVT = (const __half*)(att_smem + (buf ? SVT1B : SVT0B));

        // ---- S = Q.K^T per nb with immediate exp2 (s transient) ----
        uint32_t ph[8][2];
#pragma unroll
        for (int nb = 0; nb < 8; nb++) {
            float s4[4] = {0.f, 0.f, 0.f, 0.f};
#pragma unroll
            for (int kb = 0; kb < 4; kb++) {
                uint32_t b0 = *(uint32_t*)&sK[(nb * 8 + r) * PADH + kb * 16 + 2 * cl];
                uint32_t b1 = *(uint32_t*)&sK[(nb * 8 + r) * PADH + kb * 16 + 2 * cl + 8];
                mma_f16(s4, qa[kb][0], qa[kb][1], qa[kb][2], qa[kb][3], b0, b1);
            }
            float p0 = exp2f(s4[0]);
            float p1 = exp2f(s4[1]);
            float p2 = exp2f(s4[2]);
            float p3 = exp2f(s4[3]);
            l0 += p0 + p1;
            l1 += p2 + p3;
            ph[nb][0] = pack_h2(p0, p1);
            ph[nb][1] = pack_h2(p2, p3);
        }

        // ---- O += P.V : A = P from registers ----
#pragma unroll
        for (int kb = 0; kb < 4; kb++) {
            uint32_t a0 = ph[2 * kb][0];
            uint32_t a1 = ph[2 * kb][1];
            uint32_t a2 = ph[2 * kb + 1][0];
            uint32_t a3 = ph[2 * kb + 1][1];
#pragma unroll
            for (int nb = 0; nb < 8; nb++) {
                uint32_t b0 = *(uint32_t*)&sVT[(nb * 8 + r) * PADH + kb * 16 + 2 * cl];
                uint32_t b1 = *(uint32_t*)&sVT[(nb * 8 + r) * PADH + kb * 16 + 2 * cl + 8];
                mma_f16(o[nb], a0, a1, a2, a3, b0, b1);
            }
        }
    }

    l0 += __shfl_xor_sync(0xffffffffu, l0, 1);
    l0 += __shfl_xor_sync(0xffffffffu, l0, 2);
    l1 += __shfl_xor_sync(0xffffffffu, l1, 1);
    l1 += __shfl_xor_sync(0xffffffffu, l1, 2);
    const float inv0 = 1.0f / l0;
    const float inv1 = 1.0f / l1;

    __syncthreads();   // done reading K/VT buffers (sO overlays them)
#pragma unroll
    for (int nb = 0; nb < 8; nb++) {
        *(float2*)&sO[qrow * PADP + nb * 8 + 2 * cl] =
            make_float2(o[nb][0] * inv0, o[nb][1] * inv0);
        *(float2*)&sO[(qrow + 8) * PADP + nb * 8 + 2 * cl] =
            make_float2(o[nb][2] * inv1, o[nb][3] * inv1);
    }
    __syncthreads();

    // write O as hi/lo halves: g_ah/g_al [b][n0+row][h*64 + d]
    {
        const int row = t >> 1;
        const int seg = (t & 1) * 32;
        const float* src = sO + row * PADP + seg;
        const size_t base = ((size_t)b * N_TOK + n0 + row) * INNER + h * DH + seg;
#pragma unroll
        for (int c4 = 0; c4 < 4; c4++) {
            uint32_t uh[4], ul[4];
#pragma unroll
            for (int j = 0; j < 4; j++) {
                float v0 = src[c4 * 8 + 2 * j];
                float v1 = src[c4 * 8 + 2 * j + 1];
                __half h0 = __float2half_rn(v0);
                __half h1 = __float2half_rn(v1);
                uh[j] = pack2h(h0, h1);
                ul[j] = pack_h2(v0 - __half2float(h0), v1 - __half2float(h1));
            }
            *(uint4*)&g_ah[base + c4 * 8] = make_uint4(uh[0], uh[1], uh[2], uh[3]);
            *(uint4*)&g_al[base + c4 * 8] = make_uint4(ul[0], ul[1], ul[2], ul[3]);
        }
    }
}

// ---------------------------------------------------------------------------
// Kernel C: output projection via split-fp16 mma (3-term), double-buffered.
// (R15 version: 256 threads, 8 warps = 4(o) x 2(n).)
// ---------------------------------------------------------------------------
extern __shared__ char out_smem[];
__global__ __launch_bounds__(256, 2) void out_mma_kernel(const float* __restrict__ bias,
                                                         float* __restrict__ out) {
    const int nt = blockIdx.x;   // 0..17
    const int ot = blockIdx.y;   // 0..3
    const int b  = blockIdx.z;
    const int n0 = nt * 128;
    const int o0 = ot * 64;

    const int t    = threadIdx.x;
    const int lane = t & 31;
    const int wid  = t >> 5;
    const int wo   = wid & 3;
    const int wn   = wid >> 2;
    const int r    = lane >> 2;
    const int cl   = lane & 3;
    const int orow = wo * 16 + r;

    const int grow = t >> 1, gseg = (t & 1) * 32;
    const int wr = t >> 2, wseg = (t & 3) * 16;
    const __half* Gh = g_ah + ((size_t)b * N_TOK + n0 + grow) * INNER + gseg;
    const __half* Gl = g_al + ((size_t)b * N_TOK + n0 + grow) * INNER + gseg;
    const __half* Wh = g_woh + (size_t)(o0 + wr) * INNER + wseg;
    const __half* Wl = g_wol + (size_t)(o0 + wr) * INNER + wseg;

    const uint32_t sbase = smem_u32(out_smem);
    const uint32_t gdh = sbase + (QXH_OFF + grow * QPADC + gseg) * 2;
    const uint32_t gdl = sbase + (QXL_OFF + grow * QPADC + gseg) * 2;
    const uint32_t wdh = sbase + (QWH_OFF + wr * QPADC + wseg) * 2;
    const uint32_t wdl = sbase + (QWL_OFF + wr * QPADC + wseg) * 2;

    float acc[8][4] = {};

    // prologue: stage 0
    {
#pragma unroll
        for (int k = 0; k < 4; k++) {
            cp16(gdh + k * 16, Gh + k * 8);
            cp16(gdl + k * 16, Gl + k * 8);
        }
        cp16(wdh, Wh);      cp16(wdh + 16, Wh + 8);
        cp16(wdl, Wl);      cp16(wdl + 16, Wl + 8);
        CP_COMMIT();
    }

    for (int it = 0; it < 8; it++) {
        const uint32_t stB = (uint32_t)(it & 1) * (QSTAGE_H * 2);
        CP_WAIT0();
        __syncthreads();

        if (it < 7) {
            const int c1 = (it + 1) * 64;
            const uint32_t nsB = (uint32_t)((it + 1) & 1) * (QSTAGE_H * 2);
#pragma unroll
            for (int k = 0; k < 4; k++) {
                cp16(gdh + nsB + k * 16, Gh + c1 + k * 8);
                cp16(gdl + nsB + k * 16, Gl + c1 + k * 8);
            }
            cp16(wdh + nsB, Wh + c1);      cp16(wdh + nsB + 16, Wh + c1 + 8);
            cp16(wdl + nsB, Wl + c1);      cp16(wdl + nsB + 16, Wl + c1 + 8);
            CP_COMMIT();
        }

        const __half* sGh = (const __half*)(out_smem + stB) + QXH_OFF;
        const __half* sGl = (const __half*)(out_smem + stB) + QXL_OFF;
        const __half* sWh = (const __half*)(out_smem + stB) + QWH_OFF;
        const __half* sWl = (const __half*)(out_smem + stB) + QWL_OFF;

#pragma unroll
        for (int kc = 0; kc < 4; kc++) {
            uint32_t ah[4], al[4];
            ah[0] = *(uint32_t*)&sWh[orow * QPADC + kc * 16 + 2 * cl];
            ah[1] = *(uint32_t*)&sWh[(orow + 8) * QPADC + kc * 16 + 2 * cl];
            ah[2] = *(uint32_t*)&sWh[orow * QPADC + kc * 16 + 2 * cl + 8];
            ah[3] = *(uint32_t*)&sWh[(orow + 8) * QPADC + kc * 16 + 2 * cl + 8];
            al[0] = *(uint32_t*)&sWl[orow * QPADC + kc * 16 + 2 * cl];
            al[1] = *(uint32_t*)&sWl[(orow + 8) * QPADC + kc * 16 + 2 * cl];
            al[2] = *(uint32_t*)&sWl[orow * QPADC + kc * 16 + 2 * cl + 8];
            al[3] = *(uint32_t*)&sWl[(orow + 8) * QPADC + kc * 16 + 2 * cl + 8];
#pragma unroll
            for (int nb = 0; nb < 8; nb++) {
                int gn = wn * 64 + nb * 8 + r;
                uint32_t bh0 = *(uint32_t*)&sGh[gn * QPADC + kc * 16 + 2 * cl];
                uint32_t bh1 = *(uint32_t*)&sGh[gn * QPADC + kc * 16 + 2 * cl + 8];
                uint32_t bl0 = *(uint32_t*)&sGl[gn * QPADC + kc * 16 + 2 * cl];
                uint32_t bl1 = *(uint32_t*)&sGl[gn * QPADC + kc * 16 + 2 * cl + 8];
                mma_f16(acc[nb], ah[0], ah[1], ah[2], ah[3], bh0, bh1);
                mma_f16(acc[nb], ah[0], ah[1], ah[2], ah[3], bl0, bl1);
                mma_f16(acc[nb], al[0], al[1], al[2], al[3], bh0, bh1);
            }
        }
    }

    const int o_g = o0 + orow;
    const float bi0 = bias[o_g];
    const float bi1 = bias[o_g + 8];
    float* ob0 = out + ((size_t)b * CC + o_g) * N_TOK + n0 + wn * 64;
    float* ob1 = ob0 + 8 * N_TOK;
#pragma unroll
    for (int nb = 0; nb < 8; nb++) {
        *(float2*)&ob0[nb * 8 + 2 * cl] = make_float2(acc[nb][0] + bi0, acc[nb][1] + bi0);
        *(float2*)&ob1[nb * 8 + 2 * cl] = make_float2(acc[nb][2] + bi1, acc[nb][3] + bi1);
    }
}

// ---------------------------------------------------------------------------
extern "C" void kernel_launch(void* const* d_in, const int* in_sizes, int n_in,
                              void* d_out, int out_size) {
    const float* x    = (const float*)d_in[0];
    const float* wqkv = (const float*)d_in[1];
    const float* wout = (const float*)d_in[2];
    const float* bout = (const float*)d_in[3];
    float* out = (float*)d_out;

    (void)in_sizes; (void)n_in; (void)out_size;

    cudaFuncSetAttribute(qkv_mma_kernel, cudaFuncAttributeMaxDynamicSharedMemorySize,
                         QSMEM_BYTES);
    cudaFuncSetAttribute(attn_mma_kernel, cudaFuncAttributeMaxDynamicSharedMemorySize,
                         ATT_SMEM_BYTES);
    cudaFuncSetAttribute(out_mma_kernel, cudaFuncAttributeMaxDynamicSharedMemorySize,
                         QSMEM_BYTES);

    convert_w_kernel<<<(3 * INNER * CC + CC * INNER) / 256, 256>>>(wqkv, wout);
    convert_x_kernel<<<dim3(N_TOK / 32, CC / 32, BATCH), 256>>>(x);
    qkv_mma_kernel<<<dim3(18, 24, 4), 256, QSMEM_BYTES>>>();
    attn_mma_kernel<<<dim3(18, 8, 4), 256, ATT_SMEM_BYTES>>>();
    out_mma_kernel<<<dim3(18, 4, 4), 256, QSMEM_BYTES>>>(bout, out);
}